// round 15
// baseline (speedup 1.0000x reference)
#include <cuda_runtime.h>
#include <cuda_fp16.h>
#include <cstdint>

#define NUM_H 16
#define SEQ_T 2048
#define DIM   1024
#define HD    64

// ---------------- scratch (__device__ globals, all fp16) -------------------
__device__ __align__(16) __half gA[SEQ_T][DIM];
__device__ __align__(16) __half gBq[3 * DIM][DIM];   // [N][K]
__device__ __align__(16) __half gBp[DIM][DIM];
__device__ __align__(16) __half gY[SEQ_T][DIM];
__device__ __align__(16) __half gQ[NUM_H][SEQ_T][HD];   // pre-scaled by 1/8
__device__ __align__(16) __half gK[NUM_H][SEQ_T][HD];
__device__ __align__(16) __half gV[NUM_H][SEQ_T][HD];

// ---------------- PTX helpers ----------------------------------------------
__device__ __forceinline__ uint32_t smem_u32(const void* p) {
    uint32_t a;
    asm("{ .reg .u64 t; cvta.to.shared.u64 t, %1; cvt.u32.u64 %0, t; }" : "=r"(a) : "l"(p));
    return a;
}
#define CP_ASYNC16(dst, src) \
    asm volatile("cp.async.cg.shared.global [%0], [%1], 16;" :: "r"(dst), "l"(src))
#define CP_COMMIT() asm volatile("cp.async.commit_group;" ::: "memory")
#define CP_WAIT(n)  asm volatile("cp.async.wait_group %0;" :: "n"(n) : "memory")

__device__ __forceinline__ void ldsm4(uint32_t* r, uint32_t addr) {
    asm volatile("ldmatrix.sync.aligned.m8n8.x4.shared.b16 {%0,%1,%2,%3}, [%4];"
        : "=r"(r[0]), "=r"(r[1]), "=r"(r[2]), "=r"(r[3]) : "r"(addr));
}
__device__ __forceinline__ void ldsm4t(uint32_t* r, uint32_t addr) {
    asm volatile("ldmatrix.sync.aligned.m8n8.x4.trans.shared.b16 {%0,%1,%2,%3}, [%4];"
        : "=r"(r[0]), "=r"(r[1]), "=r"(r[2]), "=r"(r[3]) : "r"(addr));
}
__device__ __forceinline__ void mma16816(float* d, const uint32_t* a,
                                         uint32_t b0, uint32_t b1) {
    asm volatile("mma.sync.aligned.m16n8k16.row.col.f32.f16.f16.f32 "
        "{%0,%1,%2,%3}, {%4,%5,%6,%7}, {%8,%9}, {%0,%1,%2,%3};"
        : "+f"(d[0]), "+f"(d[1]), "+f"(d[2]), "+f"(d[3])
        : "r"(a[0]), "r"(a[1]), "r"(a[2]), "r"(a[3]), "r"(b0), "r"(b1));
}
__device__ __forceinline__ uint32_t pack2h(float x, float y) {
    __half2 t = __floats2half2_rn(x, y);
    return *(uint32_t*)&t;
}

// ---------------- merged prep kernel (conv + both transposes) --------------
#define PREP_BLOCKS (2048 + 3072 + 1024)

__global__ void prep_kernel(const float* __restrict__ x,
                            const float* __restrict__ Wqkv,
                            const float* __restrict__ Wproj)
{
    const int bid = blockIdx.x;
    const int tid = threadIdx.x;
    if (bid < 2048) {
        int i = (bid * 256 + tid) * 4;
        float4 v = *(const float4*)(x + i);
        __half* dst = &gA[0][0];
        *(uint32_t*)(dst + i)     = pack2h(v.x, v.y);
        *(uint32_t*)(dst + i + 2) = pack2h(v.z, v.w);
        return;
    }
    const float* W;
    __half* dst;
    int N, b2;
    if (bid < 5120) { W = Wqkv;  dst = &gBq[0][0]; N = 3 * DIM; b2 = bid - 2048; }
    else            { W = Wproj; dst = &gBp[0][0]; N = DIM;     b2 = bid - 5120; }
    const int nb = N / 32;
    const int n0 = (b2 % nb) * 32, k0 = (b2 / nb) * 32;
    const int tx = tid & 31, ty = tid >> 5;     // 32 x 8
    __shared__ float t[32][33];
    #pragma unroll
    for (int i = ty; i < 32; i += 8)
        t[i][tx] = W[(size_t)(k0 + i) * N + n0 + tx];
    __syncthreads();
    #pragma unroll
    for (int i = ty; i < 32; i += 8)
        dst[(size_t)(n0 + i) * DIM + k0 + tx] = __float2half_rn(t[tx][i]);
}

// ---------------- warp-mma fp16 GEMM, KCHUNK=64, single-sync pipeline ------
// CTA tile (64*MIW) x 128, 256 threads, 4x2 warp grid, warp tile (16*MIW)x64.
// One __syncthreads per chunk: WAIT -> sync -> issue(c+2) -> compute.
// MODE 0 (MIW=2): A=gA,B=gBq -> fp16 scatter into gQ/gK/gV (q*0.125)
// MODE 1 (MIW=1): A=gY,B=gBp -> fp32 C
#define KCHUNK   64
#define GRSTR    72                       // halves per smem row (144 B)
#define TILE_BB  (128 * GRSTR * 2)        // B tile: 18432 B

template<int MODE, int MIW>
__global__ __launch_bounds__(256)
void mma_gemm_kernel(float* __restrict__ C, int N)
{
    constexpr int AROWS   = 64 * MIW;
    constexpr int TILE_AB = AROWS * GRSTR * 2;
    constexpr int STAGE_B = TILE_AB + TILE_BB;
    extern __shared__ char smem[];
    const uint32_t sb = smem_u32(smem);
    const int tid = threadIdx.x;
    const int bm = blockIdx.y, bn = blockIdx.x;
    const int w = tid >> 5, lane = tid & 31;
    const int wm = w >> 1, wn = w & 1;            // 4 x 2 warp grid
    const int lrow = lane & 15, lcol8 = (lane >> 4) * 8;
    const int gid = lane >> 2, tig = lane & 3;

    const __half* A = (MODE == 0) ? &gA[0][0] : &gY[0][0];
    const __half* B = (MODE == 0) ? &gBq[0][0] : &gBp[0][0];

    // slots: A = AROWS*8 (= 512*MIW), B = 1024; (2*MIW + 4) per thread
    auto issue_load = [&](int c) {
        const uint32_t st = sb + (uint32_t)(c % 3) * STAGE_B;
        const int k0 = c * KCHUNK;
        #pragma unroll
        for (int it = 0; it < 2 * MIW + 4; ++it) {
            const int idx = it * 256 + tid;
            const __half* src;
            uint32_t dst;
            if (idx < AROWS * 8) {
                const int r = idx >> 3, seg = idx & 7;
                src = A + (size_t)(bm * AROWS + r) * DIM + k0 + seg * 8;
                dst = st + r * (GRSTR * 2) + seg * 16;
            } else {
                const int j = idx - AROWS * 8;
                const int r = j >> 3, seg = j & 7;
                src = B + (size_t)(bn * 128 + r) * DIM + k0 + seg * 8;
                dst = st + TILE_AB + r * (GRSTR * 2) + seg * 16;
            }
            CP_ASYNC16(dst, src);
        }
        CP_COMMIT();
    };

    float acc[MIW][8][4] = {};

    issue_load(0);
    issue_load(1);
    const int NCHUNK = DIM / KCHUNK;              // 16
    for (int c = 0; c < NCHUNK; ++c) {
        if (c + 1 < NCHUNK) { CP_WAIT(1); } else { CP_WAIT(0); }
        __syncthreads();
        if (c + 2 < NCHUNK) issue_load(c + 2);

        const uint32_t st = sb + (uint32_t)(c % 3) * STAGE_B;
        const uint32_t aB = st, bB = st + TILE_AB;

        #pragma unroll
        for (int kk = 0; kk < 4; ++kk) {
            const uint32_t koff = (kk * 16 + lcol8) * 2;
            uint32_t af[MIW][4], bf[4][4];
            #pragma unroll
            for (int mi = 0; mi < MIW; ++mi) {
                const uint32_t ro = (wm * (16 * MIW) + mi * 16 + lrow) * (GRSTR * 2) + koff;
                ldsm4(af[mi], aB + ro);
            }
            #pragma unroll
            for (int nq = 0; nq < 4; ++nq) {
                const uint32_t ro = (wn * 64 + nq * 16 + lrow) * (GRSTR * 2) + koff;
                ldsm4(bf[nq], bB + ro);
            }
            #pragma unroll
            for (int mi = 0; mi < MIW; ++mi)
                #pragma unroll
                for (int nq = 0; nq < 4; ++nq) {
                    mma16816(acc[mi][nq * 2 + 0], af[mi], bf[nq][0], bf[nq][2]);
                    mma16816(acc[mi][nq * 2 + 1], af[mi], bf[nq][1], bf[nq][3]);
                }
        }
        // no trailing sync: next iter's post-WAIT sync precedes buffer overwrite
    }

    #pragma unroll
    for (int mi = 0; mi < MIW; ++mi)
        #pragma unroll
        for (int nj = 0; nj < 8; ++nj) {
            const int row = bm * AROWS + wm * (16 * MIW) + mi * 16 + gid;
            const int n = bn * 128 + wn * 64 + nj * 8 + tig * 2;
            if (MODE == 0) {
                const int which = n >> 10;
                const int h = (n >> 6) & (NUM_H - 1);
                const int cc = n & (HD - 1);
                __half* dst = (which == 0) ? &gQ[h][0][0]
                            : (which == 1) ? &gK[h][0][0] : &gV[h][0][0];
                const float s = (which == 0) ? 0.125f : 1.0f;
                *(uint32_t*)&dst[(size_t)row * HD + cc] =
                    pack2h(acc[mi][nj][0] * s, acc[mi][nj][1] * s);
                *(uint32_t*)&dst[(size_t)(row + 8) * HD + cc] =
                    pack2h(acc[mi][nj][2] * s, acc[mi][nj][3] * s);
            } else {
                *(float2*)&C[(size_t)row * N + n] =
                    make_float2(acc[mi][nj][0], acc[mi][nj][1]);
                *(float2*)&C[(size_t)(row + 8) * N + n] =
                    make_float2(acc[mi][nj][2], acc[mi][nj][3]);
            }
        }
}

#define GEMM_SMEM_QKV (3 * (128 * GRSTR * 2 + TILE_BB))   // 110592 B
#define GEMM_SMEM_PRJ (3 * (64 * GRSTR * 2 + TILE_BB))    // 82944 B

// ---------------- flash attention, fp16 mma, single-sync KV pipeline -------
// CTA: 128 queries x 1 head. 8 warps, warp = 16 query rows.
// Bc=64 keys/iter; Q fragments hoisted; one __syncthreads per iteration.
#define BR 128
#define BC 64
#define FSTR 72                                // smem row stride in halves
#define Q_TILE_H  (BR * FSTR)                  // 9216 halves
#define KV_TILE_H (BC * FSTR)                  // 4608 halves
#define STAGE_H   (2 * KV_TILE_H)              // K | V
#define FLASH_SMEM_B ((Q_TILE_H + 3 * STAGE_H) * 2)   // 73728 B

__global__ __launch_bounds__(256)
void flash_mma_kernel()
{
    extern __shared__ char fsm[];
    const uint32_t sb = smem_u32(fsm);
    const int tid = threadIdx.x;
    const int qb = blockIdx.x, h = blockIdx.y;
    const int w = tid >> 5, lane = tid & 31;
    const int gid = lane >> 2, tig = lane & 3;
    const int l15 = lane & 15, l16 = lane >> 4;

    // one-time Q load: 1024 slots (128 rows x 8 chunks), 4 per thread
    #pragma unroll
    for (int it = 0; it < 4; ++it) {
        int idx = it * 256 + tid;
        int r = idx >> 3, ch = idx & 7;
        CP_ASYNC16(sb + (r * FSTR + ch * 8) * 2, &gQ[h][qb * BR + r][ch * 8]);
    }
    CP_COMMIT();

    auto load_kv = [&](int kb) {
        const uint32_t st = sb + (Q_TILE_H + (uint32_t)(kb % 3) * STAGE_H) * 2;
        #pragma unroll
        for (int it = 0; it < 4; ++it) {
            int idx = it * 256 + tid;
            int tile = idx >> 9, r = (idx >> 3) & 63, ch = idx & 7;
            const int tg = kb * BC + r;
            const __half* src = (tile == 0) ? &gK[h][tg][ch * 8] : &gV[h][tg][ch * 8];
            CP_ASYNC16(st + (tile * KV_TILE_H + r * FSTR + ch * 8) * 2, src);
        }
        CP_COMMIT();
    };

    float o[8][4] = {};
    float m0 = -1e30f, m1 = -1e30f, l0 = 0.f, l1 = 0.f;
    uint32_t qf[4][4];          // hoisted Q fragments (loop-invariant)

    load_kv(0);
    load_kv(1);
    const int NKB = SEQ_T / BC;                 // 32
    for (int kb = 0; kb < NKB; ++kb) {
        if (kb + 1 < NKB) { CP_WAIT(1); } else { CP_WAIT(0); }
        __syncthreads();
        if (kb + 2 < NKB) load_kv(kb + 2);

        if (kb == 0) {          // Q retired with the first wait; load frags once
            #pragma unroll
            for (int ks = 0; ks < 4; ++ks) {
                const uint32_t qoff = ((w * 16 + l15) * FSTR + ks * 16 + l16 * 8) * 2;
                ldsm4(qf[ks], sb + qoff);
            }
        }

        const uint32_t st = sb + (Q_TILE_H + (uint32_t)(kb % 3) * STAGE_H) * 2;
        const uint32_t k_b = st;
        const uint32_t v_b = st + KV_TILE_H * 2;

        // ---- S = Q K^T ----
        float s[8][4] = {};
        #pragma unroll
        for (int ks = 0; ks < 4; ++ks) {
            uint32_t kf[4][4];
            #pragma unroll
            for (int kg = 0; kg < 4; ++kg) {
                const uint32_t koff = ((kg * 16 + l15) * FSTR + ks * 16 + l16 * 8) * 2;
                ldsm4(kf[kg], k_b + koff);
            }
            #pragma unroll
            for (int kg = 0; kg < 4; ++kg) {
                mma16816(s[2 * kg],     qf[ks], kf[kg][0], kf[kg][2]);
                mma16816(s[2 * kg + 1], qf[ks], kf[kg][1], kf[kg][3]);
            }
        }

        // ---- online softmax (rows gid and gid+8 of this warp) ----
        float mx0 = -1e30f, mx1 = -1e30f;
        #pragma unroll
        for (int nf = 0; nf < 8; ++nf) {
            mx0 = fmaxf(mx0, fmaxf(s[nf][0], s[nf][1]));
            mx1 = fmaxf(mx1, fmaxf(s[nf][2], s[nf][3]));
        }
        mx0 = fmaxf(mx0, __shfl_xor_sync(0xffffffffu, mx0, 1));
        mx0 = fmaxf(mx0, __shfl_xor_sync(0xffffffffu, mx0, 2));
        mx1 = fmaxf(mx1, __shfl_xor_sync(0xffffffffu, mx1, 1));
        mx1 = fmaxf(mx1, __shfl_xor_sync(0xffffffffu, mx1, 2));
        const float mn0 = fmaxf(m0, mx0), mn1 = fmaxf(m1, mx1);
        const float c0 = __expf(m0 - mn0), c1 = __expf(m1 - mn1);
        m0 = mn0; m1 = mn1;
        float sum0 = 0.f, sum1 = 0.f;
        #pragma unroll
        for (int nf = 0; nf < 8; ++nf) {
            s[nf][0] = __expf(s[nf][0] - mn0);
            s[nf][1] = __expf(s[nf][1] - mn0);
            s[nf][2] = __expf(s[nf][2] - mn1);
            s[nf][3] = __expf(s[nf][3] - mn1);
            sum0 += s[nf][0] + s[nf][1];
            sum1 += s[nf][2] + s[nf][3];
        }
        sum0 += __shfl_xor_sync(0xffffffffu, sum0, 1);
        sum0 += __shfl_xor_sync(0xffffffffu, sum0, 2);
        sum1 += __shfl_xor_sync(0xffffffffu, sum1, 1);
        sum1 += __shfl_xor_sync(0xffffffffu, sum1, 2);
        l0 = l0 * c0 + sum0;
        l1 = l1 * c1 + sum1;
        #pragma unroll
        for (int nf = 0; nf < 8; ++nf) {
            o[nf][0] *= c0; o[nf][1] *= c0;
            o[nf][2] *= c1; o[nf][3] *= c1;
        }

        // ---- O += P V (P packed from S accumulator, V via ldmatrix.trans) --
        #pragma unroll
        for (int ks = 0; ks < 4; ++ks) {
            uint32_t pf[4];
            pf[0] = pack2h(s[2 * ks][0],     s[2 * ks][1]);
            pf[1] = pack2h(s[2 * ks][2],     s[2 * ks][3]);
            pf[2] = pack2h(s[2 * ks + 1][0], s[2 * ks + 1][1]);
            pf[3] = pack2h(s[2 * ks + 1][2], s[2 * ks + 1][3]);
            uint32_t vf[4][4];
            #pragma unroll
            for (int hg = 0; hg < 4; ++hg) {
                const uint32_t voff = ((ks * 16 + l15) * FSTR + hg * 16 + l16 * 8) * 2;
                ldsm4t(vf[hg], v_b + voff);
            }
            #pragma unroll
            for (int hg = 0; hg < 4; ++hg) {
                mma16816(o[2 * hg],     pf, vf[hg][0], vf[hg][1]);
                mma16816(o[2 * hg + 1], pf, vf[hg][2], vf[hg][3]);
            }
        }
        // no trailing sync: next iter's post-WAIT sync precedes buffer overwrite
    }

    // ---- epilogue: y = O / l -> gY fp16 ----
    const float i0 = 1.0f / l0, i1 = 1.0f / l1;
    const int t0 = qb * BR + w * 16 + gid;
    #pragma unroll
    for (int nf = 0; nf < 8; ++nf) {
        const int col = h * 64 + nf * 8 + 2 * tig;
        *(uint32_t*)&gY[t0][col]     = pack2h(o[nf][0] * i0, o[nf][1] * i0);
        *(uint32_t*)&gY[t0 + 8][col] = pack2h(o[nf][2] * i1, o[nf][3] * i1);
    }
}

// ---------------- launch ---------------------------------------------------
extern "C" void kernel_launch(void* const* d_in, const int* in_sizes, int n_in,
                              void* d_out, int out_size)
{
    (void)in_sizes; (void)n_in; (void)out_size;
    const float* x     = (const float*)d_in[0];
    const float* Wqkv  = (const float*)d_in[1];
    const float* Wproj = (const float*)d_in[2];
    float* out = (float*)d_out;

    cudaFuncSetAttribute((const void*)mma_gemm_kernel<0, 2>,
                         cudaFuncAttributeMaxDynamicSharedMemorySize, GEMM_SMEM_QKV);
    cudaFuncSetAttribute((const void*)mma_gemm_kernel<1, 1>,
                         cudaFuncAttributeMaxDynamicSharedMemorySize, GEMM_SMEM_PRJ);
    cudaFuncSetAttribute(flash_mma_kernel,
                         cudaFuncAttributeMaxDynamicSharedMemorySize, FLASH_SMEM_B);

    prep_kernel<<<PREP_BLOCKS, 256>>>(x, Wqkv, Wproj);

    // QKV = x @ W_qkv -> fp16 gQ/gK/gV   (128x128 tiles)
    mma_gemm_kernel<0, 2><<<dim3(3 * DIM / 128, SEQ_T / 128), 256, GEMM_SMEM_QKV>>>(
        nullptr, 3 * DIM);

    // fused attention -> gY fp16
    flash_mma_kernel<<<dim3(SEQ_T / BR, NUM_H), 256, FLASH_SMEM_B>>>();

    // out = y @ W_proj (fp32 out)   (64x128 tiles -> 256 CTAs, no idle SMs)
    mma_gemm_kernel<1, 1><<<dim3(DIM / 128, SEQ_T / 64), 256, GEMM_SMEM_PRJ>>>(
        out, DIM);
}

// round 16
// speedup vs baseline: 1.0548x; 1.0548x over previous
#include <cuda_runtime.h>
#include <cuda_fp16.h>
#include <cstdint>

#define NUM_H 16
#define SEQ_T 2048
#define DIM   1024
#define HD    64

// ---------------- scratch (__device__ globals, all fp16) -------------------
__device__ __align__(16) __half gA[SEQ_T][DIM];
__device__ __align__(16) __half gWq[DIM][3 * DIM];   // [K][N] (native W layout)
__device__ __align__(16) __half gWp[DIM][DIM];       // [K][N]
__device__ __align__(16) __half gY[SEQ_T][DIM];
__device__ __align__(16) __half gQ[NUM_H][SEQ_T][HD];   // pre-scaled by 1/8
__device__ __align__(16) __half gK[NUM_H][SEQ_T][HD];
__device__ __align__(16) __half gV[NUM_H][SEQ_T][HD];

// ---------------- PTX helpers ----------------------------------------------
__device__ __forceinline__ uint32_t smem_u32(const void* p) {
    uint32_t a;
    asm("{ .reg .u64 t; cvta.to.shared.u64 t, %1; cvt.u32.u64 %0, t; }" : "=r"(a) : "l"(p));
    return a;
}
#define CP_ASYNC16(dst, src) \
    asm volatile("cp.async.cg.shared.global [%0], [%1], 16;" :: "r"(dst), "l"(src))
#define CP_COMMIT() asm volatile("cp.async.commit_group;" ::: "memory")
#define CP_WAIT(n)  asm volatile("cp.async.wait_group %0;" :: "n"(n) : "memory")

__device__ __forceinline__ void ldsm4(uint32_t* r, uint32_t addr) {
    asm volatile("ldmatrix.sync.aligned.m8n8.x4.shared.b16 {%0,%1,%2,%3}, [%4];"
        : "=r"(r[0]), "=r"(r[1]), "=r"(r[2]), "=r"(r[3]) : "r"(addr));
}
__device__ __forceinline__ void ldsm4t(uint32_t* r, uint32_t addr) {
    asm volatile("ldmatrix.sync.aligned.m8n8.x4.trans.shared.b16 {%0,%1,%2,%3}, [%4];"
        : "=r"(r[0]), "=r"(r[1]), "=r"(r[2]), "=r"(r[3]) : "r"(addr));
}
__device__ __forceinline__ void mma16816(float* d, const uint32_t* a,
                                         uint32_t b0, uint32_t b1) {
    asm volatile("mma.sync.aligned.m16n8k16.row.col.f32.f16.f16.f32 "
        "{%0,%1,%2,%3}, {%4,%5,%6,%7}, {%8,%9}, {%0,%1,%2,%3};"
        : "+f"(d[0]), "+f"(d[1]), "+f"(d[2]), "+f"(d[3])
        : "r"(a[0]), "r"(a[1]), "r"(a[2]), "r"(a[3]), "r"(b0), "r"(b1));
}
__device__ __forceinline__ uint32_t pack2h(float x, float y) {
    __half2 t = __floats2half2_rn(x, y);
    return *(uint32_t*)&t;
}

// ---------------- prep: pure linear fp32 -> fp16 conversions ---------------
// blocks [0,2048): x -> gA ; [2048,5120): Wqkv -> gWq ; [5120,6144): Wproj -> gWp
#define PREP_BLOCKS (2048 + 3072 + 1024)

__global__ void prep_kernel(const float* __restrict__ x,
                            const float* __restrict__ Wqkv,
                            const float* __restrict__ Wproj)
{
    const int bid = blockIdx.x;
    const int tid = threadIdx.x;
    const float* src;
    __half* dst;
    int i;
    if (bid < 2048)      { src = x;     dst = &gA[0][0];  i = (bid * 256 + tid) * 4; }
    else if (bid < 5120) { src = Wqkv;  dst = &gWq[0][0]; i = ((bid - 2048) * 256 + tid) * 4; }
    else                 { src = Wproj; dst = &gWp[0][0]; i = ((bid - 5120) * 256 + tid) * 4; }
    float4 v = *(const float4*)(src + i);
    *(uint32_t*)(dst + i)     = pack2h(v.x, v.y);
    *(uint32_t*)(dst + i + 2) = pack2h(v.z, v.w);
}

// ---------------- warp-mma fp16 GEMM, trans-B from [K][N] ------------------
// CTA 128x128, 256 threads, 4x2 warp grid, warp tile 32x64, KCHUNK=64.
// A [M][K] non-trans ldsm; B [K][N] via ldmatrix.trans (no weight transpose).
// Single-sync 3-stage pipeline: WAIT -> sync -> issue(c+2) -> compute.
// MODE 0: A=gA,B=gWq -> fp16 scatter into gQ/gK/gV (q*0.125)
// MODE 1: A=gY,B=gWp -> fp32 C
#define KCHUNK   64
#define GRSTR    72                       // A smem row stride (halves)
#define BSTR     136                      // B smem row stride (halves), 17x16B odd
#define TILE_AB  (128 * GRSTR * 2)        // 18432 B
#define TILE_BB  (KCHUNK * BSTR * 2)      // 17408 B
#define STAGE_B  (TILE_AB + TILE_BB)      // 35840 B
#define GEMM_SMEM (3 * STAGE_B)           // 107520 B

template<int MODE>
__global__ __launch_bounds__(256)
void mma_gemm_kernel(float* __restrict__ C, int N)
{
    extern __shared__ char smem[];
    const uint32_t sb = smem_u32(smem);
    const int tid = threadIdx.x;
    const int bm = blockIdx.y, bn = blockIdx.x;
    const int w = tid >> 5, lane = tid & 31;
    const int wm = w >> 1, wn = w & 1;            // 4 x 2 warp grid
    const int lrow = lane & 15, lcol8 = (lane >> 4) * 8;
    const int l15 = lane & 15, l16 = lane >> 4;
    const int gid = lane >> 2, tig = lane & 3;

    const __half* A = (MODE == 0) ? &gA[0][0] : &gY[0][0];
    const __half* B = (MODE == 0) ? &gWq[0][0] : &gWp[0][0];

    // slots: A = 128 rows x 8 segs = 1024 ; B = 64 k-rows x 16 segs = 1024
    auto issue_load = [&](int c) {
        const uint32_t st = sb + (uint32_t)(c % 3) * STAGE_B;
        const int k0 = c * KCHUNK;
        #pragma unroll
        for (int it = 0; it < 8; ++it) {
            const int idx = it * 256 + tid;
            const __half* src;
            uint32_t dst;
            if (idx < 1024) {       // A tile: [128 m][64 k]
                const int r = idx >> 3, seg = idx & 7;
                src = A + (size_t)(bm * 128 + r) * DIM + k0 + seg * 8;
                dst = st + r * (GRSTR * 2) + seg * 16;
            } else {                // B tile: [64 k][128 n] from W[K][N]
                const int j = idx - 1024;
                const int r = j >> 4, seg = j & 15;
                src = B + (size_t)(k0 + r) * N + bn * 128 + seg * 8;
                dst = st + TILE_AB + r * (BSTR * 2) + seg * 16;
            }
            CP_ASYNC16(dst, src);
        }
        CP_COMMIT();
    };

    float acc[2][8][4] = {};

    issue_load(0);
    issue_load(1);
    const int NCHUNK = DIM / KCHUNK;              // 16
    for (int c = 0; c < NCHUNK; ++c) {
        if (c + 1 < NCHUNK) { CP_WAIT(1); } else { CP_WAIT(0); }
        __syncthreads();
        if (c + 2 < NCHUNK) issue_load(c + 2);

        const uint32_t st = sb + (uint32_t)(c % 3) * STAGE_B;
        const uint32_t aB = st, bB = st + TILE_AB;

        #pragma unroll
        for (int kk = 0; kk < 4; ++kk) {
            const uint32_t koff = (kk * 16 + lcol8) * 2;
            uint32_t af[2][4], bf[4][4];
            #pragma unroll
            for (int mi = 0; mi < 2; ++mi) {
                const uint32_t ro = (wm * 32 + mi * 16 + lrow) * (GRSTR * 2) + koff;
                ldsm4(af[mi], aB + ro);
            }
            #pragma unroll
            for (int nq = 0; nq < 4; ++nq) {
                const uint32_t ro = ((kk * 16 + l15) * BSTR
                                   + wn * 64 + nq * 16 + l16 * 8) * 2;
                ldsm4t(bf[nq], bB + ro);
            }
            #pragma unroll
            for (int mi = 0; mi < 2; ++mi)
                #pragma unroll
                for (int nq = 0; nq < 4; ++nq) {
                    mma16816(acc[mi][nq * 2 + 0], af[mi], bf[nq][0], bf[nq][1]);
                    mma16816(acc[mi][nq * 2 + 1], af[mi], bf[nq][2], bf[nq][3]);
                }
        }
        // no trailing sync: next iter's post-WAIT sync precedes buffer overwrite
    }

    #pragma unroll
    for (int mi = 0; mi < 2; ++mi)
        #pragma unroll
        for (int nj = 0; nj < 8; ++nj) {
            const int row = bm * 128 + wm * 32 + mi * 16 + gid;
            const int n = bn * 128 + wn * 64 + nj * 8 + tig * 2;
            if (MODE == 0) {
                const int which = n >> 10;
                const int h = (n >> 6) & (NUM_H - 1);
                const int cc = n & (HD - 1);
                __half* dst = (which == 0) ? &gQ[h][0][0]
                            : (which == 1) ? &gK[h][0][0] : &gV[h][0][0];
                const float s = (which == 0) ? 0.125f : 1.0f;
                *(uint32_t*)&dst[(size_t)row * HD + cc] =
                    pack2h(acc[mi][nj][0] * s, acc[mi][nj][1] * s);
                *(uint32_t*)&dst[(size_t)(row + 8) * HD + cc] =
                    pack2h(acc[mi][nj][2] * s, acc[mi][nj][3] * s);
            } else {
                *(float2*)&C[(size_t)row * N + n] =
                    make_float2(acc[mi][nj][0], acc[mi][nj][1]);
                *(float2*)&C[(size_t)(row + 8) * N + n] =
                    make_float2(acc[mi][nj][2], acc[mi][nj][3]);
            }
        }
}

// ---------------- flash attention, fp16 mma, single-sync KV pipeline -------
#define BR 128
#define BC 64
#define FSTR 72                                // smem row stride in halves
#define Q_TILE_H  (BR * FSTR)                  // 9216 halves
#define KV_TILE_H (BC * FSTR)                  // 4608 halves
#define STAGE_H   (2 * KV_TILE_H)              // K | V
#define FLASH_SMEM_B ((Q_TILE_H + 3 * STAGE_H) * 2)   // 73728 B

__global__ __launch_bounds__(256)
void flash_mma_kernel()
{
    extern __shared__ char fsm[];
    const uint32_t sb = smem_u32(fsm);
    const int tid = threadIdx.x;
    const int qb = blockIdx.x, h = blockIdx.y;
    const int w = tid >> 5, lane = tid & 31;
    const int gid = lane >> 2, tig = lane & 3;
    const int l15 = lane & 15, l16 = lane >> 4;

    // one-time Q load: 1024 slots (128 rows x 8 chunks), 4 per thread
    #pragma unroll
    for (int it = 0; it < 4; ++it) {
        int idx = it * 256 + tid;
        int r = idx >> 3, ch = idx & 7;
        CP_ASYNC16(sb + (r * FSTR + ch * 8) * 2, &gQ[h][qb * BR + r][ch * 8]);
    }
    CP_COMMIT();

    auto load_kv = [&](int kb) {
        const uint32_t st = sb + (Q_TILE_H + (uint32_t)(kb % 3) * STAGE_H) * 2;
        #pragma unroll
        for (int it = 0; it < 4; ++it) {
            int idx = it * 256 + tid;
            int tile = idx >> 9, r = (idx >> 3) & 63, ch = idx & 7;
            const int tg = kb * BC + r;
            const __half* src = (tile == 0) ? &gK[h][tg][ch * 8] : &gV[h][tg][ch * 8];
            CP_ASYNC16(st + (tile * KV_TILE_H + r * FSTR + ch * 8) * 2, src);
        }
        CP_COMMIT();
    };

    float o[8][4] = {};
    float m0 = -1e30f, m1 = -1e30f, l0 = 0.f, l1 = 0.f;
    uint32_t qf[4][4];          // hoisted Q fragments (loop-invariant)

    load_kv(0);
    load_kv(1);
    const int NKB = SEQ_T / BC;                 // 32
    for (int kb = 0; kb < NKB; ++kb) {
        if (kb + 1 < NKB) { CP_WAIT(1); } else { CP_WAIT(0); }
        __syncthreads();
        if (kb + 2 < NKB) load_kv(kb + 2);

        if (kb == 0) {          // Q retired with the first wait; load frags once
            #pragma unroll
            for (int ks = 0; ks < 4; ++ks) {
                const uint32_t qoff = ((w * 16 + l15) * FSTR + ks * 16 + l16 * 8) * 2;
                ldsm4(qf[ks], sb + qoff);
            }
        }

        const uint32_t st = sb + (Q_TILE_H + (uint32_t)(kb % 3) * STAGE_H) * 2;
        const uint32_t k_b = st;
        const uint32_t v_b = st + KV_TILE_H * 2;

        // ---- S = Q K^T ----
        float s[8][4] = {};
        #pragma unroll
        for (int ks = 0; ks < 4; ++ks) {
            uint32_t kf[4][4];
            #pragma unroll
            for (int kg = 0; kg < 4; ++kg) {
                const uint32_t koff = ((kg * 16 + l15) * FSTR + ks * 16 + l16 * 8) * 2;
                ldsm4(kf[kg], k_b + koff);
            }
            #pragma unroll
            for (int kg = 0; kg < 4; ++kg) {
                mma16816(s[2 * kg],     qf[ks], kf[kg][0], kf[kg][2]);
                mma16816(s[2 * kg + 1], qf[ks], kf[kg][1], kf[kg][3]);
            }
        }

        // ---- online softmax (rows gid and gid+8 of this warp) ----
        float mx0 = -1e30f, mx1 = -1e30f;
        #pragma unroll
        for (int nf = 0; nf < 8; ++nf) {
            mx0 = fmaxf(mx0, fmaxf(s[nf][0], s[nf][1]));
            mx1 = fmaxf(mx1, fmaxf(s[nf][2], s[nf][3]));
        }
        mx0 = fmaxf(mx0, __shfl_xor_sync(0xffffffffu, mx0, 1));
        mx0 = fmaxf(mx0, __shfl_xor_sync(0xffffffffu, mx0, 2));
        mx1 = fmaxf(mx1, __shfl_xor_sync(0xffffffffu, mx1, 1));
        mx1 = fmaxf(mx1, __shfl_xor_sync(0xffffffffu, mx1, 2));
        const float mn0 = fmaxf(m0, mx0), mn1 = fmaxf(m1, mx1);
        const float c0 = __expf(m0 - mn0), c1 = __expf(m1 - mn1);
        m0 = mn0; m1 = mn1;
        float sum0 = 0.f, sum1 = 0.f;
        #pragma unroll
        for (int nf = 0; nf < 8; ++nf) {
            s[nf][0] = __expf(s[nf][0] - mn0);
            s[nf][1] = __expf(s[nf][1] - mn0);
            s[nf][2] = __expf(s[nf][2] - mn1);
            s[nf][3] = __expf(s[nf][3] - mn1);
            sum0 += s[nf][0] + s[nf][1];
            sum1 += s[nf][2] + s[nf][3];
        }
        sum0 += __shfl_xor_sync(0xffffffffu, sum0, 1);
        sum0 += __shfl_xor_sync(0xffffffffu, sum0, 2);
        sum1 += __shfl_xor_sync(0xffffffffu, sum1, 1);
        sum1 += __shfl_xor_sync(0xffffffffu, sum1, 2);
        l0 = l0 * c0 + sum0;
        l1 = l1 * c1 + sum1;
        #pragma unroll
        for (int nf = 0; nf < 8; ++nf) {
            o[nf][0] *= c0; o[nf][1] *= c0;
            o[nf][2] *= c1; o[nf][3] *= c1;
        }

        // ---- O += P V (P packed from S accumulator, V via ldmatrix.trans) --
        #pragma unroll
        for (int ks = 0; ks < 4; ++ks) {
            uint32_t pf[4];
            pf[0] = pack2h(s[2 * ks][0],     s[2 * ks][1]);
            pf[1] = pack2h(s[2 * ks][2],     s[2 * ks][3]);
            pf[2] = pack2h(s[2 * ks + 1][0], s[2 * ks + 1][1]);
            pf[3] = pack2h(s[2 * ks + 1][2], s[2 * ks + 1][3]);
            uint32_t vf[4][4];
            #pragma unroll
            for (int hg = 0; hg < 4; ++hg) {
                const uint32_t voff = ((ks * 16 + l15) * FSTR + hg * 16 + l16 * 8) * 2;
                ldsm4t(vf[hg], v_b + voff);
            }
            #pragma unroll
            for (int hg = 0; hg < 4; ++hg) {
                mma16816(o[2 * hg],     pf, vf[hg][0], vf[hg][1]);
                mma16816(o[2 * hg + 1], pf, vf[hg][2], vf[hg][3]);
            }
        }
        // no trailing sync: next iter's post-WAIT sync precedes buffer overwrite
    }

    // ---- epilogue: y = O / l -> gY fp16 ----
    const float i0 = 1.0f / l0, i1 = 1.0f / l1;
    const int t0 = qb * BR + w * 16 + gid;
    #pragma unroll
    for (int nf = 0; nf < 8; ++nf) {
        const int col = h * 64 + nf * 8 + 2 * tig;
        *(uint32_t*)&gY[t0][col]     = pack2h(o[nf][0] * i0, o[nf][1] * i0);
        *(uint32_t*)&gY[t0 + 8][col] = pack2h(o[nf][2] * i1, o[nf][3] * i1);
    }
}

// ---------------- launch ---------------------------------------------------
extern "C" void kernel_launch(void* const* d_in, const int* in_sizes, int n_in,
                              void* d_out, int out_size)
{
    (void)in_sizes; (void)n_in; (void)out_size;
    const float* x     = (const float*)d_in[0];
    const float* Wqkv  = (const float*)d_in[1];
    const float* Wproj = (const float*)d_in[2];
    float* out = (float*)d_out;

    cudaFuncSetAttribute(mma_gemm_kernel<0>, cudaFuncAttributeMaxDynamicSharedMemorySize,
                         GEMM_SMEM);
    cudaFuncSetAttribute(mma_gemm_kernel<1>, cudaFuncAttributeMaxDynamicSharedMemorySize,
                         GEMM_SMEM);
    cudaFuncSetAttribute(flash_mma_kernel, cudaFuncAttributeMaxDynamicSharedMemorySize,
                         FLASH_SMEM_B);

    prep_kernel<<<PREP_BLOCKS, 256>>>(x, Wqkv, Wproj);

    // QKV = x @ W_qkv -> fp16 gQ/gK/gV   (128x128 tiles, B from [K][N])
    mma_gemm_kernel<0><<<dim3(3 * DIM / 128, SEQ_T / 128), 256, GEMM_SMEM>>>(
        nullptr, 3 * DIM);

    // fused attention -> gY fp16
    flash_mma_kernel<<<dim3(SEQ_T / BR, NUM_H), 256, FLASH_SMEM_B>>>();

    // out = y @ W_proj (fp32 out)  (128x128 tiles, measured faster than 64x128)
    mma_gemm_kernel<1><<<dim3(DIM / 128, SEQ_T / 128), 256, GEMM_SMEM>>>(
        out, DIM);
}